// round 15
// baseline (speedup 1.0000x reference)
#include <cuda_runtime.h>
#include <cuda_fp16.h>
#include <math.h>
#include <stdint.h>

#define Bsz 2048
#define Nn  20
#define Dd  512
#define Hh  8
#define M_TOT (Bsz*Nn)   // 40960
#define KC 1536
#define NC 1536
#define NCP 1664         // 1536 qkv + 64 qf + 64 zero = 13*128

// ---------------- device scratch ----------------
__device__ __half g_x_h[(size_t)M_TOT * Dd];
__device__ __half g_wpt[(size_t)NCP * KC];
__device__ __half g_wot[(size_t)Dd * Dd];
__device__ float g_qkv[(size_t)M_TOT * NC];
__device__ float g_qf[(size_t)M_TOT * 64];
__device__ float g_av[(size_t)M_TOT * 8];
__device__ __half g_att_h[(size_t)M_TOT * Dd];

// ---------------- helpers ----------------
__device__ __forceinline__ uint32_t smem_u32(const void* p) {
    uint32_t a;
    asm("{ .reg .u64 t; cvta.to.shared.u64 t, %1; cvt.u32.u64 %0, t; }" : "=r"(a) : "l"(p));
    return a;
}
#define LDSM4(r, addr) \
    asm volatile("ldmatrix.sync.aligned.m8n8.x4.shared.b16 {%0,%1,%2,%3}, [%4];" \
        : "=r"((r)[0]), "=r"((r)[1]), "=r"((r)[2]), "=r"((r)[3]) : "r"(addr))

__device__ __forceinline__ void mma16816(float* d, const uint32_t* a, const uint32_t* b) {
    asm volatile(
        "mma.sync.aligned.m16n8k16.row.col.f32.f16.f16.f32 "
        "{%0,%1,%2,%3}, {%4,%5,%6,%7}, {%8,%9}, {%0,%1,%2,%3};"
        : "+f"(d[0]), "+f"(d[1]), "+f"(d[2]), "+f"(d[3])
        : "r"(a[0]), "r"(a[1]), "r"(a[2]), "r"(a[3]), "r"(b[0]), "r"(b[1]));
}
__device__ __forceinline__ void cp16(uint32_t dst, const void* src, uint32_t sz) {
    asm volatile("cp.async.cg.shared.global [%0], [%1], 16, %2;" :: "r"(dst), "l"(src), "r"(sz) : "memory");
}
#define CP_COMMIT() asm volatile("cp.async.commit_group;" ::: "memory")

// ---------------- conversions / packing ----------------
__global__ void x2h(const float* __restrict__ x) {
    size_t i = (size_t)(blockIdx.x * blockDim.x + threadIdx.x);
    float4 v = ((const float4*)x)[i];
    __half2* o = (__half2*)g_x_h;
    o[i * 2]     = __floats2half2_rn(v.x, v.y);
    o[i * 2 + 1] = __floats2half2_rn(v.z, v.w);
}

__global__ void pack_w_t(const float* __restrict__ Wq, const float* __restrict__ Wk,
                         const float* __restrict__ Wv, const float* __restrict__ Wqf) {
    int idx = blockIdx.x * blockDim.x + threadIdx.x;
    if (idx >= NCP * KC) return;
    int j = idx / KC, k = idx - (idx / KC) * KC;
    float w = 0.f;
    if (j < NC) {
        int p = j >> 9, o = j & 511;
        int s = k >> 9, i = k & 511;
        const float* W = (p == 0) ? Wq : (p == 1 ? Wk : Wv);
        w = W[(o * Dd + i) * 3 + s];
    } else if (j < NC + 64) {
        int jj = j - NC;
        if ((k >> 9) == 1) w = Wqf[(k & 511) * 64 + jj];
    }
    g_wpt[(size_t)j * KC + k] = __float2half_rn(w);
}

__global__ void pack_wo_t(const float* __restrict__ Wo) {
    int idx = blockIdx.x * blockDim.x + threadIdx.x;
    int j = idx >> 9, k = idx & 511;
    g_wot[(size_t)j * Dd + k] = __float2half_rn(Wo[(size_t)k * Dd + j]);
}

// ---------------- mma.sync GEMM: 128x128 tiles, K=32, 4-stage cp.async ----------------
#define ROWP 40
#define MATB (128 * ROWP * 2)          // 10240 B
#define STAGE_B (2 * MATB)             // 20480 B
#define GSMEM (4 * STAGE_B)            // 81920 B

template<int KDIM, bool CONV>
__global__ __launch_bounds__(256, 2) void mma_gemm(float* __restrict__ Cout,
                                                   const float* __restrict__ bias,
                                                   const float* __restrict__ bqf,
                                                   int moff) {
    extern __shared__ char smc[];
    const uint32_t sbase = smem_u32(smc);
    const int tid = threadIdx.x;
    const int bm = (blockIdx.y + moff) * 128, bn = blockIdx.x * 128;
    const int NCH = KDIM / 32;

    const __half* Ah = CONV ? g_x_h : g_att_h;
    const __half* Bh = CONV ? g_wpt : g_wot;

    // qf tile (bn >= NC): packed B nonzero only for k in [512,1024) -> chunks 16..31
    int cbeg = 0, cend = NCH;
    if (CONV && bn >= NC) { cbeg = 16; cend = 32; }

    auto load_stage = [&](int c) {
        const int k0 = c * 32;
        const uint32_t sb = sbase + (c & 3) * STAGE_B;
        #pragma unroll
        for (int i = 0; i < 4; i++) {
            int t = tid + i * 256;
            int mat = t >> 9, idx = t & 511, row = idx >> 2, q = idx & 3;
            uint32_t dst = sb + mat * MATB + (row * ROWP + q * 8) * 2;
            const __half* src;
            uint32_t sz = 16;
            if (mat == 0) {
                if (CONV) {
                    int m = bm + row;
                    int b = m / Nn, n = m - b * Nn;
                    int sn = n + (k0 >> 9) - 1;
                    int snc = sn < 0 ? 0 : (sn >= Nn ? Nn - 1 : sn);
                    if (sn != snc) sz = 0;
                    src = Ah + (((size_t)(b * Nn + snc)) << 9) + (k0 & 511) + q * 8;
                } else {
                    src = Ah + (size_t)(bm + row) * KDIM + k0 + q * 8;
                }
            } else {
                src = Bh + (size_t)(bn + row) * KDIM + k0 + q * 8;
            }
            cp16(dst, src, sz);
        }
        CP_COMMIT();
    };

    const int lane = tid & 31, wid = tid >> 5;
    const int wm = (wid >> 2) * 64, wn = (wid & 3) * 32;
    float acc[4][4][4];
    #pragma unroll
    for (int a = 0; a < 4; a++)
        #pragma unroll
        for (int b = 0; b < 4; b++)
            #pragma unroll
            for (int d = 0; d < 4; d++) acc[a][b][d] = 0.f;

    load_stage(cbeg); load_stage(cbeg + 1); load_stage(cbeg + 2);

    for (int c = cbeg; c < cend; c++) {
        if (c + 2 < cend)      asm volatile("cp.async.wait_group 2;" ::: "memory");
        else if (c + 1 < cend) asm volatile("cp.async.wait_group 1;" ::: "memory");
        else                   asm volatile("cp.async.wait_group 0;" ::: "memory");
        __syncthreads();
        if (c + 3 < cend) load_stage(c + 3);

        const uint32_t sb = sbase + (c & 3) * STAGE_B;
        #pragma unroll
        for (int kk = 0; kk < 2; kk++) {
            const int koff = kk * 16 + ((lane >> 4) << 3);
            const int arow = lane & 15;
            uint32_t a_h[4][4], b_h[4][2];
            #pragma unroll
            for (int mt = 0; mt < 4; mt++) {
                uint32_t ad = sb + ((wm + mt * 16 + arow) * ROWP + koff) * 2;
                LDSM4(a_h[mt], ad);
            }
            const int brow = ((lane >> 4) << 3) + (lane & 7);
            const int bkoff = kk * 16 + (((lane >> 3) & 1) << 3);
            #pragma unroll
            for (int pr = 0; pr < 2; pr++) {
                uint32_t bd = sb + MATB + ((wn + pr * 16 + brow) * ROWP + bkoff) * 2;
                uint32_t r[4];
                LDSM4(r, bd);
                b_h[pr * 2][0] = r[0]; b_h[pr * 2][1] = r[1];
                b_h[pr * 2 + 1][0] = r[2]; b_h[pr * 2 + 1][1] = r[3];
            }
            #pragma unroll
            for (int mt = 0; mt < 4; mt++)
                #pragma unroll
                for (int nt = 0; nt < 4; nt++)
                    mma16816(acc[mt][nt], a_h[mt], b_h[nt]);
        }
    }

    // ---------------- epilogue ----------------
    const int g = lane >> 2, tg = lane & 3;
    #pragma unroll
    for (int mt = 0; mt < 4; mt++) {
        #pragma unroll
        for (int nt = 0; nt < 4; nt++) {
            int j = bn + wn + nt * 8 + tg * 2;
            #pragma unroll
            for (int half = 0; half < 2; half++) {
                int m = bm + wm + mt * 16 + g + half * 8;
                float d0 = acc[mt][nt][half * 2], d1 = acc[mt][nt][half * 2 + 1];
                if (CONV) {
                    if (j < NC) {
                        *(float2*)(g_qkv + (size_t)m * NC + j) = make_float2(d0, d1);
                    } else if (j < NC + 64) {
                        int jj = j - NC;
                        *(float2*)(g_qf + (size_t)m * 64 + jj) =
                            make_float2(tanhf(d0 + bqf[jj]), tanhf(d1 + bqf[jj + 1]));
                    }
                } else {
                    *(float2*)(Cout + (size_t)m * KDIM + j) =
                        make_float2(d0 + bias[j], d1 + bias[j + 1]);
                }
            }
        }
    }
}

// ---------------- LayerNorm + residual, in place on g_qkv (float4) ----------------
__global__ void ln_res(const float* __restrict__ x,
                       const float* g0, const float* b0,
                       const float* g1, const float* b1,
                       const float* g2, const float* b2) {
    int m = blockIdx.x, p = blockIdx.y;
    const float* g  = (p == 0) ? g0 : (p == 1 ? g1 : g2);
    const float* bb = (p == 0) ? b0 : (p == 1 ? b1 : b2);
    float* row = g_qkv + (size_t)m * NC + p * Dd;
    int tid = threadIdx.x;          // 128 threads
    float4 v = ((const float4*)row)[tid];
    float s = v.x + v.y + v.z + v.w;
    float s2 = v.x * v.x + v.y * v.y + v.z * v.z + v.w * v.w;
    #pragma unroll
    for (int o = 16; o; o >>= 1) {
        s  += __shfl_xor_sync(0xffffffffu, s, o);
        s2 += __shfl_xor_sync(0xffffffffu, s2, o);
    }
    __shared__ float ss[4], ss2[4];
    int w = tid >> 5, l = tid & 31;
    if (l == 0) { ss[w] = s; ss2[w] = s2; }
    __syncthreads();
    if (tid == 0) {
        float t = ss[0] + ss[1] + ss[2] + ss[3];
        float t2 = ss2[0] + ss2[1] + ss2[2] + ss2[3];
        float mean = t * (1.f / 512.f);
        float var = t2 * (1.f / 512.f) - mean * mean;
        ss[0] = mean; ss2[0] = rsqrtf(var + 1e-5f);
    }
    __syncthreads();
    float mean = ss[0], inv = ss2[0];
    float4 xv = ((const float4*)(x + (size_t)m * Dd))[tid];
    float4 gv = ((const float4*)g)[tid];
    float4 bv = ((const float4*)bb)[tid];
    float4 o;
    o.x = xv.x + (v.x - mean) * inv * gv.x + bv.x;
    o.y = xv.y + (v.y - mean) * inv * gv.y + bv.y;
    o.z = xv.z + (v.z - mean) * inv * gv.z + bv.z;
    o.w = xv.w + (v.w - mean) * inv * gv.w + bv.w;
    ((float4*)row)[tid] = o;
}

// ---------------- av[m][h] = qf[m] . Wqp[:,h] ----------------
__global__ void av_kernel(const float* __restrict__ Wqp) {
    int t = blockIdx.x * blockDim.x + threadIdx.x;   // over M_TOT*8
    int m = t >> 3, h = t & 7;
    const float* qf = g_qf + (size_t)m * 64;
    float a = 0.f;
    #pragma unroll 16
    for (int j = 0; j < 64; j++) a += qf[j] * Wqp[j * 8 + h];
    g_av[t] = a;
}

// ---------------- attention per (b, h), small smem, high occupancy ----------------
#define NPAD 65
__global__ __launch_bounds__(128) void attn_small(const float* __restrict__ rel,
                                                  const float* __restrict__ gsb,
                                                  const float* __restrict__ alpha_p,
                                                  const float* __restrict__ bqp,
                                                  int bh_off) {
    __shared__ float qs[20 * NPAD], ks[20 * NPAD], vs[20 * NPAD];
    __shared__ float sc[400], av[20];
    const int bh = blockIdx.x + bh_off;
    const int b = bh >> 3, h = bh & 7;
    const size_t row0 = (size_t)b * Nn;
    const int tid = threadIdx.x;

    for (int i = tid; i < 1280; i += 128) {
        int n = i >> 6, d = i & 63;
        size_t base = (row0 + n) * NC + h * 64 + d;
        int o = n * NPAD + d;
        qs[o] = g_qkv[base];
        ks[o] = g_qkv[base + 512];
        vs[o] = g_qkv[base + 1024];
    }
    if (tid < 20) av[tid] = g_av[(row0 + tid) * 8 + h];
    __syncthreads();

    const float alpha = *alpha_p, bq = bqp[h];
    for (int t = tid; t < 400; t += 128) {
        int nq = t / 20, nk = t - nq * 20;
        const float* q = qs + nq * NPAD;
        const float* k = ks + nk * NPAD;
        float d = 0.f;
        #pragma unroll 16
        for (int j = 0; j < 64; j++) d += q[j] * k[j];
        sc[t] = d * 0.125f
              + rel[(nq - nk + 19) * 8 + h]
              + alpha * gsb[h * 400 + t]
              + (av[nq] - av[nk] + bq);
    }
    __syncthreads();

    if (tid < 20) {
        float* row = sc + tid * 20;
        float mx = -1e30f;
        #pragma unroll
        for (int k = 0; k < 20; k++) mx = fmaxf(mx, row[k]);
        float s = 0.f;
        #pragma unroll
        for (int k = 0; k < 20; k++) { float e = expf(row[k] - mx); row[k] = e; s += e; }
        float inv = 1.f / s;
        #pragma unroll
        for (int k = 0; k < 20; k++) row[k] *= inv;
    }
    __syncthreads();

    for (int i = tid; i < 1280; i += 128) {
        int n = i >> 6, d = i & 63;
        const float* a = sc + n * 20;
        float o = 0.f;
        #pragma unroll
        for (int nk = 0; nk < 20; nk++) o += a[nk] * vs[nk * NPAD + d];
        g_att_h[(row0 + n) * Dd + h * 64 + d] = __float2half_rn(o);
    }
}

extern "C" void kernel_launch(void* const* d_in, const int* in_sizes, int n_in,
                              void* d_out, int out_size) {
    const float* x   = (const float*)d_in[0];
    const float* Wq  = (const float*)d_in[1];
    const float* Wk  = (const float*)d_in[2];
    const float* Wv  = (const float*)d_in[3];
    const float* gqg = (const float*)d_in[4];
    const float* gqb = (const float*)d_in[5];
    const float* gkg = (const float*)d_in[6];
    const float* gkb = (const float*)d_in[7];
    const float* gvg = (const float*)d_in[8];
    const float* gvb = (const float*)d_in[9];
    const float* rel = (const float*)d_in[10];
    const float* gsb = (const float*)d_in[11];
    const float* alp = (const float*)d_in[12];
    const float* Wqf = (const float*)d_in[13];
    const float* bqf = (const float*)d_in[14];
    const float* Wqp = (const float*)d_in[15];
    const float* bqp = (const float*)d_in[16];
    const float* Wo  = (const float*)d_in[17];
    const float* bo  = (const float*)d_in[18];
    float* out = (float*)d_out;

    static cudaStream_t s1 = nullptr;
    static cudaEvent_t ev0, evW, evWo, evC, evAV, evA0, evO0;
    static int inited = 0;
    if (!inited) {
        cudaFuncSetAttribute(mma_gemm<KC, true>,  cudaFuncAttributeMaxDynamicSharedMemorySize, GSMEM);
        cudaFuncSetAttribute(mma_gemm<Dd, false>, cudaFuncAttributeMaxDynamicSharedMemorySize, GSMEM);
        cudaStreamCreateWithFlags(&s1, cudaStreamNonBlocking);
        cudaEventCreateWithFlags(&ev0,  cudaEventDisableTiming);
        cudaEventCreateWithFlags(&evW,  cudaEventDisableTiming);
        cudaEventCreateWithFlags(&evWo, cudaEventDisableTiming);
        cudaEventCreateWithFlags(&evC,  cudaEventDisableTiming);
        cudaEventCreateWithFlags(&evAV, cudaEventDisableTiming);
        cudaEventCreateWithFlags(&evA0, cudaEventDisableTiming);
        cudaEventCreateWithFlags(&evO0, cudaEventDisableTiming);
        inited = 1;
    }

    // ---- fork side stream ----
    cudaEventRecord(ev0, 0);
    cudaStreamWaitEvent(s1, ev0, 0);

    // side: pack_w -> pack_wo
    pack_w_t<<<(NCP * KC + 255) / 256, 256, 0, s1>>>(Wq, Wk, Wv, Wqf);
    cudaEventRecord(evW, s1);
    pack_wo_t<<<(Dd * Dd) / 256, 256, 0, s1>>>(Wo);
    cudaEventRecord(evWo, s1);

    // main: x2h ; conv (needs x2h + pack_w)
    x2h<<<(M_TOT * Dd) / 1024, 256>>>(x);
    cudaStreamWaitEvent(0, evW, 0);
    dim3 g1(NCP / 128, M_TOT / 128);   // 13 x 320
    mma_gemm<KC, true><<<g1, 256, GSMEM>>>(nullptr, nullptr, bqf, 0);
    cudaEventRecord(evC, 0);

    // side: av (needs conv)
    cudaStreamWaitEvent(s1, evC, 0);
    av_kernel<<<(M_TOT * 8) / 256, 256, 0, s1>>>(Wqp);
    cudaEventRecord(evAV, s1);

    // main: ln_res ; attn halves
    dim3 g2(M_TOT, 3);
    ln_res<<<g2, 128>>>(x, gqg, gqb, gkg, gkb, gvg, gvb);
    cudaStreamWaitEvent(0, evAV, 0);
    attn_small<<<Bsz * Hh / 2, 128>>>(rel, gsb, alp, bqp, 0);            // batches 0..1023
    cudaEventRecord(evA0, 0);
    attn_small<<<Bsz * Hh / 2, 128>>>(rel, gsb, alp, bqp, Bsz * Hh / 2); // batches 1024..2047

    // side: out half 0 (m rows 0..20479) — needs attn half 0 + pack_wo (in-order on s1)
    cudaStreamWaitEvent(s1, evA0, 0);
    dim3 g3(Dd / 128, M_TOT / 256);    // 4 x 160
    mma_gemm<Dd, false><<<g3, 256, GSMEM, s1>>>(out, bo, nullptr, 0);
    cudaEventRecord(evO0, s1);

    // main: out half 1 (m rows 20480..40959) — needs attn half 1 + pack_wo
    cudaStreamWaitEvent(0, evWo, 0);
    mma_gemm<Dd, false><<<g3, 256, GSMEM>>>(out, bo, nullptr, 160);

    // join side stream
    cudaStreamWaitEvent(0, evO0, 0);
}

// round 17
// speedup vs baseline: 1.0995x; 1.0995x over previous
#include <cuda_runtime.h>
#include <cuda_fp16.h>
#include <math.h>
#include <stdint.h>

#define Bsz 2048
#define Nn  20
#define Dd  512
#define Hh  8
#define M_TOT (Bsz*Nn)   // 40960
#define KC 1536
#define NC 1536
#define NCP 1664         // 1536 qkv + 64 qf + 64 zero

// ---------------- device scratch ----------------
__device__ __half g_x_h[(size_t)M_TOT * Dd];
__device__ __half g_wpt[(size_t)NCP * KC];
__device__ __half g_wot[(size_t)Dd * Dd];
__device__ float g_qkv[(size_t)M_TOT * NC];
__device__ float g_qf[(size_t)M_TOT * 64];
__device__ float g_av[(size_t)M_TOT * 8];
__device__ __half g_att_h[(size_t)M_TOT * Dd];

// ---------------- helpers ----------------
__device__ __forceinline__ uint32_t smem_u32(const void* p) {
    uint32_t a;
    asm("{ .reg .u64 t; cvta.to.shared.u64 t, %1; cvt.u32.u64 %0, t; }" : "=r"(a) : "l"(p));
    return a;
}
#define LDSM4(r, addr) \
    asm volatile("ldmatrix.sync.aligned.m8n8.x4.shared.b16 {%0,%1,%2,%3}, [%4];" \
        : "=r"((r)[0]), "=r"((r)[1]), "=r"((r)[2]), "=r"((r)[3]) : "r"(addr))

__device__ __forceinline__ void mma16816(float* d, const uint32_t* a, const uint32_t* b) {
    asm volatile(
        "mma.sync.aligned.m16n8k16.row.col.f32.f16.f16.f32 "
        "{%0,%1,%2,%3}, {%4,%5,%6,%7}, {%8,%9}, {%0,%1,%2,%3};"
        : "+f"(d[0]), "+f"(d[1]), "+f"(d[2]), "+f"(d[3])
        : "r"(a[0]), "r"(a[1]), "r"(a[2]), "r"(a[3]), "r"(b[0]), "r"(b[1]));
}
__device__ __forceinline__ void cp16(uint32_t dst, const void* src, uint32_t sz) {
    asm volatile("cp.async.cg.shared.global [%0], [%1], 16, %2;" :: "r"(dst), "l"(src), "r"(sz) : "memory");
}
#define CP_COMMIT() asm volatile("cp.async.commit_group;" ::: "memory")

// ---------------- conversions / packing ----------------
__global__ void x2h(const float* __restrict__ x) {
    size_t i = (size_t)(blockIdx.x * blockDim.x + threadIdx.x);
    float4 v = ((const float4*)x)[i];
    __half2* o = (__half2*)g_x_h;
    o[i * 2]     = __floats2half2_rn(v.x, v.y);
    o[i * 2 + 1] = __floats2half2_rn(v.z, v.w);
}

__global__ void pack_w_t(const float* __restrict__ Wq, const float* __restrict__ Wk,
                         const float* __restrict__ Wv, const float* __restrict__ Wqf) {
    int idx = blockIdx.x * blockDim.x + threadIdx.x;
    if (idx >= NCP * KC) return;
    int j = idx / KC, k = idx - (idx / KC) * KC;
    float w = 0.f;
    if (j < NC) {
        int p = j >> 9, o = j & 511;
        int s = k >> 9, i = k & 511;
        const float* W = (p == 0) ? Wq : (p == 1 ? Wk : Wv);
        w = W[(o * Dd + i) * 3 + s];
    } else if (j < NC + 64) {
        int jj = j - NC;
        if ((k >> 9) == 1) w = Wqf[(k & 511) * 64 + jj];
    }
    g_wpt[(size_t)j * KC + k] = __float2half_rn(w);
}

__global__ void pack_wo_t(const float* __restrict__ Wo) {
    int idx = blockIdx.x * blockDim.x + threadIdx.x;
    int j = idx >> 9, k = idx & 511;
    g_wot[(size_t)j * Dd + k] = __float2half_rn(Wo[(size_t)k * Dd + j]);
}

// ---------------- mma.sync GEMM: 128x128 tiles, K=32, 4-stage cp.async ----------------
#define ROWP 40
#define MATB (128 * ROWP * 2)          // 10240 B
#define STAGE_B (2 * MATB)             // 20480 B
#define GSMEM (4 * STAGE_B)            // 81920 B

template<int KDIM, bool CONV, int CBEG, int CEND, int BNOFF>
__global__ __launch_bounds__(256, 2) void mma_gemm(float* __restrict__ Cout,
                                                   const float* __restrict__ bias,
                                                   const float* __restrict__ bqf) {
    extern __shared__ char smc[];
    const uint32_t sbase = smem_u32(smc);
    const int tid = threadIdx.x;
    const int bm = blockIdx.y * 128, bn = blockIdx.x * 128 + BNOFF;

    const __half* Ah = CONV ? g_x_h : g_att_h;
    const __half* Bh = CONV ? g_wpt : g_wot;

    auto load_stage = [&](int c) {
        const int k0 = c * 32;
        const uint32_t sb = sbase + (c & 3) * STAGE_B;
        #pragma unroll
        for (int i = 0; i < 4; i++) {
            int t = tid + i * 256;
            int mat = t >> 9, idx = t & 511, row = idx >> 2, q = idx & 3;
            uint32_t dst = sb + mat * MATB + (row * ROWP + q * 8) * 2;
            const __half* src;
            uint32_t sz = 16;
            if (mat == 0) {
                if (CONV) {
                    int m = bm + row;
                    int b = m / Nn, n = m - b * Nn;
                    int sn = n + (k0 >> 9) - 1;
                    int snc = sn < 0 ? 0 : (sn >= Nn ? Nn - 1 : sn);
                    if (sn != snc) sz = 0;
                    src = Ah + (((size_t)(b * Nn + snc)) << 9) + (k0 & 511) + q * 8;
                } else {
                    src = Ah + (size_t)(bm + row) * KDIM + k0 + q * 8;
                }
            } else {
                src = Bh + (size_t)(bn + row) * KDIM + k0 + q * 8;
            }
            cp16(dst, src, sz);
        }
        CP_COMMIT();
    };

    const int lane = tid & 31, wid = tid >> 5;
    const int wm = (wid >> 2) * 64, wn = (wid & 3) * 32;
    float acc[4][4][4];
    #pragma unroll
    for (int a = 0; a < 4; a++)
        #pragma unroll
        for (int b = 0; b < 4; b++)
            #pragma unroll
            for (int d = 0; d < 4; d++) acc[a][b][d] = 0.f;

    load_stage(CBEG); load_stage(CBEG + 1); load_stage(CBEG + 2);

    #pragma unroll 1
    for (int c = CBEG; c < CEND; c++) {
        if (c + 2 < CEND)      asm volatile("cp.async.wait_group 2;" ::: "memory");
        else if (c + 1 < CEND) asm volatile("cp.async.wait_group 1;" ::: "memory");
        else                   asm volatile("cp.async.wait_group 0;" ::: "memory");
        __syncthreads();
        if (c + 3 < CEND) load_stage(c + 3);

        const uint32_t sb = sbase + (c & 3) * STAGE_B;
        #pragma unroll
        for (int kk = 0; kk < 2; kk++) {
            const int koff = kk * 16 + ((lane >> 4) << 3);
            const int arow = lane & 15;
            uint32_t a_h[4][4], b_h[4][2];
            #pragma unroll
            for (int mt = 0; mt < 4; mt++) {
                uint32_t ad = sb + ((wm + mt * 16 + arow) * ROWP + koff) * 2;
                LDSM4(a_h[mt], ad);
            }
            const int brow = ((lane >> 4) << 3) + (lane & 7);
            const int bkoff = kk * 16 + (((lane >> 3) & 1) << 3);
            #pragma unroll
            for (int pr = 0; pr < 2; pr++) {
                uint32_t bd = sb + MATB + ((wn + pr * 16 + brow) * ROWP + bkoff) * 2;
                uint32_t r[4];
                LDSM4(r, bd);
                b_h[pr * 2][0] = r[0]; b_h[pr * 2][1] = r[1];
                b_h[pr * 2 + 1][0] = r[2]; b_h[pr * 2 + 1][1] = r[3];
            }
            #pragma unroll
            for (int mt = 0; mt < 4; mt++)
                #pragma unroll
                for (int nt = 0; nt < 4; nt++)
                    mma16816(acc[mt][nt], a_h[mt], b_h[nt]);
        }
    }

    // ---------------- epilogue ----------------
    const int g = lane >> 2, tg = lane & 3;
    #pragma unroll
    for (int mt = 0; mt < 4; mt++) {
        #pragma unroll
        for (int nt = 0; nt < 4; nt++) {
            int j = bn + wn + nt * 8 + tg * 2;
            #pragma unroll
            for (int half = 0; half < 2; half++) {
                int m = bm + wm + mt * 16 + g + half * 8;
                float d0 = acc[mt][nt][half * 2], d1 = acc[mt][nt][half * 2 + 1];
                if (CONV) {
                    if (BNOFF < NC) {
                        *(float2*)(g_qkv + (size_t)m * NC + j) = make_float2(d0, d1);
                    } else {
                        int jj = j - NC;
                        if (jj < 64)   // upper 64 cols of qf tile are zero-pad: discard
                            *(float2*)(g_qf + (size_t)m * 64 + jj) =
                                make_float2(tanhf(d0 + bqf[jj]), tanhf(d1 + bqf[jj + 1]));
                    }
                } else {
                    *(float2*)(Cout + (size_t)m * KDIM + j) =
                        make_float2(d0 + bias[j], d1 + bias[j + 1]);
                }
            }
        }
    }
}

// ---------------- LayerNorm + residual, in place on g_qkv (float4) ----------------
__global__ void ln_res(const float* __restrict__ x,
                       const float* g0, const float* b0,
                       const float* g1, const float* b1,
                       const float* g2, const float* b2) {
    int m = blockIdx.x, p = blockIdx.y;
    const float* g  = (p == 0) ? g0 : (p == 1 ? g1 : g2);
    const float* bb = (p == 0) ? b0 : (p == 1 ? b1 : b2);
    float* row = g_qkv + (size_t)m * NC + p * Dd;
    int tid = threadIdx.x;          // 128 threads
    float4 v = ((const float4*)row)[tid];
    float s = v.x + v.y + v.z + v.w;
    float s2 = v.x * v.x + v.y * v.y + v.z * v.z + v.w * v.w;
    #pragma unroll
    for (int o = 16; o; o >>= 1) {
        s  += __shfl_xor_sync(0xffffffffu, s, o);
        s2 += __shfl_xor_sync(0xffffffffu, s2, o);
    }
    __shared__ float ss[4], ss2[4];
    int w = tid >> 5, l = tid & 31;
    if (l == 0) { ss[w] = s; ss2[w] = s2; }
    __syncthreads();
    if (tid == 0) {
        float t = ss[0] + ss[1] + ss[2] + ss[3];
        float t2 = ss2[0] + ss2[1] + ss2[2] + ss2[3];
        float mean = t * (1.f / 512.f);
        float var = t2 * (1.f / 512.f) - mean * mean;
        ss[0] = mean; ss2[0] = rsqrtf(var + 1e-5f);
    }
    __syncthreads();
    float mean = ss[0], inv = ss2[0];
    float4 xv = ((const float4*)(x + (size_t)m * Dd))[tid];
    float4 gv = ((const float4*)g)[tid];
    float4 bv = ((const float4*)bb)[tid];
    float4 o;
    o.x = xv.x + (v.x - mean) * inv * gv.x + bv.x;
    o.y = xv.y + (v.y - mean) * inv * gv.y + bv.y;
    o.z = xv.z + (v.z - mean) * inv * gv.z + bv.z;
    o.w = xv.w + (v.w - mean) * inv * gv.w + bv.w;
    ((float4*)row)[tid] = o;
}

// ---------------- av[m][h] = qf[m] . Wqp[:,h] ----------------
__global__ void av_kernel(const float* __restrict__ Wqp) {
    int t = blockIdx.x * blockDim.x + threadIdx.x;   // over M_TOT*8
    int m = t >> 3, h = t & 7;
    const float* qf = g_qf + (size_t)m * 64;
    float a = 0.f;
    #pragma unroll 16
    for (int j = 0; j < 64; j++) a += qf[j] * Wqp[j * 8 + h];
    g_av[t] = a;
}

// ---------------- attention per (b, h), small smem, high occupancy ----------------
#define NPAD 65
__global__ __launch_bounds__(128) void attn_small(const float* __restrict__ rel,
                                                  const float* __restrict__ gsb,
                                                  const float* __restrict__ alpha_p,
                                                  const float* __restrict__ bqp) {
    __shared__ float qs[20 * NPAD], ks[20 * NPAD], vs[20 * NPAD];
    __shared__ float sc[400], av[20];
    const int bh = blockIdx.x;
    const int b = bh >> 3, h = bh & 7;
    const size_t row0 = (size_t)b * Nn;
    const int tid = threadIdx.x;

    for (int i = tid; i < 1280; i += 128) {
        int n = i >> 6, d = i & 63;
        size_t base = (row0 + n) * NC + h * 64 + d;
        int o = n * NPAD + d;
        qs[o] = g_qkv[base];
        ks[o] = g_qkv[base + 512];
        vs[o] = g_qkv[base + 1024];
    }
    if (tid < 20) av[tid] = g_av[(row0 + tid) * 8 + h];
    __syncthreads();

    const float alpha = *alpha_p, bq = bqp[h];
    for (int t = tid; t < 400; t += 128) {
        int nq = t / 20, nk = t - nq * 20;
        const float* q = qs + nq * NPAD;
        const float* k = ks + nk * NPAD;
        float d = 0.f;
        #pragma unroll 16
        for (int j = 0; j < 64; j++) d += q[j] * k[j];
        sc[t] = d * 0.125f
              + rel[(nq - nk + 19) * 8 + h]
              + alpha * gsb[h * 400 + t]
              + (av[nq] - av[nk] + bq);
    }
    __syncthreads();

    if (tid < 20) {
        float* row = sc + tid * 20;
        float mx = -1e30f;
        #pragma unroll
        for (int k = 0; k < 20; k++) mx = fmaxf(mx, row[k]);
        float s = 0.f;
        #pragma unroll
        for (int k = 0; k < 20; k++) { float e = expf(row[k] - mx); row[k] = e; s += e; }
        float inv = 1.f / s;
        #pragma unroll
        for (int k = 0; k < 20; k++) row[k] *= inv;
    }
    __syncthreads();

    for (int i = tid; i < 1280; i += 128) {
        int n = i >> 6, d = i & 63;
        const float* a = sc + n * 20;
        float o = 0.f;
        #pragma unroll
        for (int nk = 0; nk < 20; nk++) o += a[nk] * vs[nk * NPAD + d];
        g_att_h[(row0 + n) * Dd + h * 64 + d] = __float2half_rn(o);
    }
}

extern "C" void kernel_launch(void* const* d_in, const int* in_sizes, int n_in,
                              void* d_out, int out_size) {
    const float* x   = (const float*)d_in[0];
    const float* Wq  = (const float*)d_in[1];
    const float* Wk  = (const float*)d_in[2];
    const float* Wv  = (const float*)d_in[3];
    const float* gqg = (const float*)d_in[4];
    const float* gqb = (const float*)d_in[5];
    const float* gkg = (const float*)d_in[6];
    const float* gkb = (const float*)d_in[7];
    const float* gvg = (const float*)d_in[8];
    const float* gvb = (const float*)d_in[9];
    const float* rel = (const float*)d_in[10];
    const float* gsb = (const float*)d_in[11];
    const float* alp = (const float*)d_in[12];
    const float* Wqf = (const float*)d_in[13];
    const float* bqf = (const float*)d_in[14];
    const float* Wqp = (const float*)d_in[15];
    const float* bqp = (const float*)d_in[16];
    const float* Wo  = (const float*)d_in[17];
    const float* bo  = (const float*)d_in[18];
    float* out = (float*)d_out;

    static cudaStream_t s1 = nullptr;
    static cudaEvent_t ev0, evW, evWo, evX, evAV;
    static int inited = 0;
    if (!inited) {
        cudaFuncSetAttribute(mma_gemm<KC, true, 0, 48, 0>,  cudaFuncAttributeMaxDynamicSharedMemorySize, GSMEM);
        cudaFuncSetAttribute(mma_gemm<KC, true, 16, 32, NC>, cudaFuncAttributeMaxDynamicSharedMemorySize, GSMEM);
        cudaFuncSetAttribute(mma_gemm<Dd, false, 0, 16, 0>, cudaFuncAttributeMaxDynamicSharedMemorySize, GSMEM);
        cudaStreamCreateWithFlags(&s1, cudaStreamNonBlocking);
        cudaEventCreateWithFlags(&ev0,  cudaEventDisableTiming);
        cudaEventCreateWithFlags(&evW,  cudaEventDisableTiming);
        cudaEventCreateWithFlags(&evWo, cudaEventDisableTiming);
        cudaEventCreateWithFlags(&evX,  cudaEventDisableTiming);
        cudaEventCreateWithFlags(&evAV, cudaEventDisableTiming);
        inited = 1;
    }

    // ---- fork side stream ----
    cudaEventRecord(ev0, 0);
    cudaStreamWaitEvent(s1, ev0, 0);

    // side: pack_w, pack_wo
    pack_w_t<<<(NCP * KC + 255) / 256, 256, 0, s1>>>(Wq, Wk, Wv, Wqf);
    cudaEventRecord(evW, s1);
    pack_wo_t<<<(Dd * Dd) / 256, 256, 0, s1>>>(Wo);
    cudaEventRecord(evWo, s1);

    // main: x2h
    x2h<<<(M_TOT * Dd) / 1024, 256>>>(x);
    cudaEventRecord(evX, 0);

    // main: conv qkv tiles (needs x2h + pack_w)
    cudaStreamWaitEvent(0, evW, 0);
    dim3 g1(12, M_TOT / 128);          // 12 x 320 (qkv only)
    mma_gemm<KC, true, 0, 48, 0><<<g1, 256, GSMEM>>>(nullptr, nullptr, bqf);

    // side: qf tile GEMM (needs x2h + pack_w; chunks 16..32 only) then av — concurrent with conv
    cudaStreamWaitEvent(s1, evX, 0);
    dim3 gq(1, M_TOT / 128);           // 1 x 320
    mma_gemm<KC, true, 16, 32, NC><<<gq, 256, GSMEM, s1>>>(nullptr, nullptr, bqf);
    av_kernel<<<(M_TOT * 8) / 256, 256, 0, s1>>>(Wqp);
    cudaEventRecord(evAV, s1);

    // main: ln_res ; attn (needs ln + av) ; out (needs attn + pack_wo)
    dim3 g2(M_TOT, 3);
    ln_res<<<g2, 128>>>(x, gqg, gqb, gkg, gkb, gvg, gvb);
    cudaStreamWaitEvent(0, evAV, 0);
    attn_small<<<Bsz * Hh, 128>>>(rel, gsb, alp, bqp);
    cudaStreamWaitEvent(0, evWo, 0);
    dim3 g3(Dd / 128, M_TOT / 128);    // 4 x 320
    mma_gemm<Dd, false, 0, 16, 0><<<g3, 256, GSMEM>>>(out, bo, nullptr);
}